// round 5
// baseline (speedup 1.0000x reference)
#include <cuda_runtime.h>
#include <cuda_bf16.h>
#include <cstdint>

#define S_ 2048
#define D_ 512
#define H_ 8
#define DK_ 64
#define BH_ 32
#define TOK_ 8192
#define OUT_ELEMS 4194304ull
#define ATTN_ELEMS 134217728ull
#define PO_ 4194304ull

__device__ uint16_t g_xnh[3ull * TOK_ * D_];
__device__ uint16_t g_xnl[3ull * TOK_ * D_];
__device__ uint16_t g_wh[4ull * 512 * 512];
__device__ uint16_t g_wl[4ull * 512 * 512];
__device__ uint16_t g_phh[3ull * PO_];
__device__ uint16_t g_phl[3ull * PO_];
__device__ uint16_t g_xh[(size_t)TOK_ * D_];
__device__ uint16_t g_xl[(size_t)TOK_ * D_];
__device__ float g_rsum[BH_ * S_];
__device__ float g_attn_scratch[ATTN_ELEMS];

__device__ __forceinline__ void hmma(float c[4], const uint32_t a[4], uint32_t b0, uint32_t b1) {
    asm("mma.sync.aligned.m16n8k16.row.col.f32.bf16.bf16.f32 "
        "{%0,%1,%2,%3},{%4,%5,%6,%7},{%8,%9},{%0,%1,%2,%3};"
        : "+f"(c[0]), "+f"(c[1]), "+f"(c[2]), "+f"(c[3])
        : "r"(a[0]), "r"(a[1]), "r"(a[2]), "r"(a[3]), "r"(b0), "r"(b1));
}
__device__ __forceinline__ void splitpack(float f0, float f1, uint32_t& h, uint32_t& l) {
    asm("cvt.rn.bf16x2.f32 %0, %1, %2;" : "=r"(h) : "f"(f1), "f"(f0));
    float g0 = __uint_as_float(h << 16);
    float g1 = __uint_as_float(h & 0xffff0000u);
    asm("cvt.rn.bf16x2.f32 %0, %1, %2;" : "=r"(l) : "f"(f1 - g1), "f"(f0 - g0));
}
__device__ __forceinline__ float fexp(float x) {
    float t = x * 1.4426950408889634f;
    t = fmaxf(t, -126.0f);
    float z = t + 12582912.0f;
    int   n = (__float_as_int(z) & 0x7FFFFF) - 0x400000;
    float f = t - (z - 12582912.0f);
    float p = 1.5403530e-4f;
    p = fmaf(p, f, 1.3333558e-3f);
    p = fmaf(p, f, 9.6181291e-3f);
    p = fmaf(p, f, 5.5504109e-2f);
    p = fmaf(p, f, 2.4022651e-1f);
    p = fmaf(p, f, 6.9314718e-1f);
    p = fmaf(p, f, 1.0f);
    return __int_as_float(__float_as_int(p) + (n << 23));
}

// ---------------- K1: LayerNorm -> split bf16 ----------------
__global__ void ln_split(const float* __restrict__ q, const float* __restrict__ k,
                         const float* __restrict__ v, const float* __restrict__ w,
                         const float* __restrict__ b,
                         uint16_t* __restrict__ xh, uint16_t* __restrict__ xl) {
    const int row = blockIdx.x, which = blockIdx.y, tid = threadIdx.x;
    const float* src = (which == 0) ? q : (which == 1) ? k : v;
    float4 x = *(const float4*)(src + (size_t)row * D_ + tid * 4);
    float s  = x.x + x.y + x.z + x.w;
    float ss = x.x * x.x + x.y * x.y + x.z * x.z + x.w * x.w;
    __shared__ float red[2][4];
    #pragma unroll
    for (int o = 16; o; o >>= 1) {
        s  += __shfl_xor_sync(0xffffffffu, s, o);
        ss += __shfl_xor_sync(0xffffffffu, ss, o);
    }
    if ((tid & 31) == 0) { red[0][tid >> 5] = s; red[1][tid >> 5] = ss; }
    __syncthreads();
    s  = red[0][0] + red[0][1] + red[0][2] + red[0][3];
    ss = red[1][0] + red[1][1] + red[1][2] + red[1][3];
    const float mu  = s * (1.0f / D_);
    const float var = ss * (1.0f / D_) - mu * mu;
    const float r   = rsqrtf(var + 1e-5f);
    float4 wv = *(const float4*)(w + tid * 4);
    float4 bv = *(const float4*)(b + tid * 4);
    float o0 = (x.x - mu) * r * wv.x + bv.x;
    float o1 = (x.y - mu) * r * wv.y + bv.y;
    float o2 = (x.z - mu) * r * wv.z + bv.z;
    float o3 = (x.w - mu) * r * wv.w + bv.w;
    uint32_t h01, l01, h23, l23;
    splitpack(o0, o1, h01, l01); splitpack(o2, o3, h23, l23);
    size_t base = ((size_t)which * TOK_ + row) * D_ + tid * 4;
    *(uint32_t*)(xh + base) = h01; *(uint32_t*)(xh + base + 2) = h23;
    *(uint32_t*)(xl + base) = l01; *(uint32_t*)(xl + base + 2) = l23;
}

// ---------------- K2: split weights ----------------
__global__ void wsplit(const float* __restrict__ Wq, const float* __restrict__ Wk,
                       const float* __restrict__ Wv, const float* __restrict__ Wo,
                       uint16_t* __restrict__ wh, uint16_t* __restrict__ wl) {
    const int row = blockIdx.x, mat = blockIdx.y, tid = threadIdx.x;
    const float* W = (mat == 0) ? Wq : (mat == 1) ? Wk : (mat == 2) ? Wv : Wo;
    float4 x = *(const float4*)(W + (size_t)row * 512 + tid * 4);
    uint32_t h01, l01, h23, l23;
    splitpack(x.x, x.y, h01, l01); splitpack(x.z, x.w, h23, l23);
    size_t base = ((size_t)mat * 512 + row) * 512 + tid * 4;
    *(uint32_t*)(wh + base) = h01; *(uint32_t*)(wh + base + 2) = h23;
    *(uint32_t*)(wl + base) = l01; *(uint32_t*)(wl + base + 2) = l23;
}

// ---------------- K3/K6: C[8192,512] = A @ W^T + bias (split-bf16 HMMA) ----------------
__global__ __launch_bounds__(256)
void gemm_mma(const uint16_t* __restrict__ Ah, const uint16_t* __restrict__ Al,
              const uint16_t* __restrict__ Bh, const uint16_t* __restrict__ Bl,
              const float* __restrict__ bias,
              uint16_t* __restrict__ Dh, uint16_t* __restrict__ Dl,
              float* __restrict__ Df, int mode) {
    extern __shared__ uint16_t sm[];
    uint16_t* sAh = sm;
    uint16_t* sAl = sm + 9216;
    uint16_t* sBh = sm + 18432;
    uint16_t* sBl = sm + 27648;
    const int tid = threadIdx.x, w = tid >> 5, lane = tid & 31;
    const int gid = lane >> 2, tig = lane & 3;
    const int n0 = blockIdx.x * 128, m0 = blockIdx.y * 128;
    const int wm = w >> 2, wn = w & 3;
    const int srow = tid >> 1, shalf = (tid & 1) * 32;
    float acc[4][4][4];
    #pragma unroll
    for (int i = 0; i < 4; i++)
        #pragma unroll
        for (int j = 0; j < 4; j++)
            #pragma unroll
            for (int kq = 0; kq < 4; kq++) acc[i][j][kq] = 0.f;

    for (int c = 0; c < 8; c++) {
        __syncthreads();
        {
            const uint4* a  = (const uint4*)(Ah + (size_t)(m0 + srow) * 512 + c * 64 + shalf);
            const uint4* a2 = (const uint4*)(Al + (size_t)(m0 + srow) * 512 + c * 64 + shalf);
            const uint4* b  = (const uint4*)(Bh + (size_t)(n0 + srow) * 512 + c * 64 + shalf);
            const uint4* b2 = (const uint4*)(Bl + (size_t)(n0 + srow) * 512 + c * 64 + shalf);
            uint4* dA  = (uint4*)(sAh + srow * 72 + shalf);
            uint4* dA2 = (uint4*)(sAl + srow * 72 + shalf);
            uint4* dB  = (uint4*)(sBh + srow * 72 + shalf);
            uint4* dB2 = (uint4*)(sBl + srow * 72 + shalf);
            #pragma unroll
            for (int j = 0; j < 4; j++) { dA[j] = a[j]; dA2[j] = a2[j]; dB[j] = b[j]; dB2[j] = b2[j]; }
        }
        __syncthreads();
        #pragma unroll
        for (int ks = 0; ks < 4; ks++) {
            const int dk = ks * 16 + 2 * tig;
            uint32_t ah[4][4], al[4][4], bhf[4][2], blf[4][2];
            #pragma unroll
            for (int mt = 0; mt < 4; mt++) {
                int ar = wm * 64 + mt * 16 + gid;
                ah[mt][0] = *(const uint32_t*)(sAh + ar * 72 + dk);
                ah[mt][1] = *(const uint32_t*)(sAh + (ar + 8) * 72 + dk);
                ah[mt][2] = *(const uint32_t*)(sAh + ar * 72 + dk + 8);
                ah[mt][3] = *(const uint32_t*)(sAh + (ar + 8) * 72 + dk + 8);
                al[mt][0] = *(const uint32_t*)(sAl + ar * 72 + dk);
                al[mt][1] = *(const uint32_t*)(sAl + (ar + 8) * 72 + dk);
                al[mt][2] = *(const uint32_t*)(sAl + ar * 72 + dk + 8);
                al[mt][3] = *(const uint32_t*)(sAl + (ar + 8) * 72 + dk + 8);
            }
            #pragma unroll
            for (int nt = 0; nt < 4; nt++) {
                int br = wn * 32 + nt * 8 + gid;
                bhf[nt][0] = *(const uint32_t*)(sBh + br * 72 + dk);
                bhf[nt][1] = *(const uint32_t*)(sBh + br * 72 + dk + 8);
                blf[nt][0] = *(const uint32_t*)(sBl + br * 72 + dk);
                blf[nt][1] = *(const uint32_t*)(sBl + br * 72 + dk + 8);
            }
            #pragma unroll
            for (int mt = 0; mt < 4; mt++)
                #pragma unroll
                for (int nt = 0; nt < 4; nt++) {
                    hmma(acc[mt][nt], ah[mt], bhf[nt][0], bhf[nt][1]);
                    hmma(acc[mt][nt], al[mt], bhf[nt][0], bhf[nt][1]);
                    hmma(acc[mt][nt], ah[mt], blf[nt][0], blf[nt][1]);
                }
        }
    }
    #pragma unroll
    for (int mt = 0; mt < 4; mt++) {
        int row0 = m0 + wm * 64 + mt * 16 + gid, row1 = row0 + 8;
        #pragma unroll
        for (int nt = 0; nt < 4; nt++) {
            int nc = n0 + wn * 32 + nt * 8 + 2 * tig;
            float b0 = bias[nc], b1 = bias[nc + 1];
            float c00 = acc[mt][nt][0] + b0, c01 = acc[mt][nt][1] + b1;
            float c10 = acc[mt][nt][2] + b0, c11 = acc[mt][nt][3] + b1;
            if (mode == 0) {
                *(float2*)(Df + (size_t)row0 * 512 + nc) = make_float2(c00, c01);
                *(float2*)(Df + (size_t)row1 * 512 + nc) = make_float2(c10, c11);
            } else {
                int h = nc >> 6, dd = nc & 63;
                uint32_t hh, ll;
                int bb = row0 >> 11, tk = row0 & 2047;
                size_t o = (((size_t)(bb * H_ + h)) * S_ + tk) * DK_ + dd;
                splitpack(c00, c01, hh, ll);
                *(uint32_t*)(Dh + o) = hh; *(uint32_t*)(Dl + o) = ll;
                bb = row1 >> 11; tk = row1 & 2047;
                o = (((size_t)(bb * H_ + h)) * S_ + tk) * DK_ + dd;
                splitpack(c10, c11, hh, ll);
                *(uint32_t*)(Dh + o) = hh; *(uint32_t*)(Dl + o) = ll;
            }
        }
    }
}

// ---------------- K4/K5: two-pass flash attention (split-bf16 HMMA) ----------------
__global__ __launch_bounds__(256)
void attn_mma(const uint16_t* __restrict__ ph, const uint16_t* __restrict__ pl,
              const float* __restrict__ pos, float* __restrict__ attn,
              float* __restrict__ rsum,
              uint16_t* __restrict__ xh, uint16_t* __restrict__ xl, int pass) {
    extern __shared__ uint16_t sm[];
    uint16_t* QH = sm;
    uint16_t* QL = sm + 9216;
    uint16_t* KH = sm + 18432;
    uint16_t* KL = sm + 27648;
    uint16_t* VTH = sm + 36864;
    uint16_t* VTL = sm + 45312;
    const int tid = threadIdx.x, w = tid >> 5, lane = tid & 31;
    const int gid = lane >> 2, tig = lane & 3;
    const int qt = blockIdx.x, bh = blockIdx.y, q0 = qt * 128;
    const uint16_t* qg  = ph;
    const uint16_t* qgl = pl;
    const uint16_t* kg  = ph + PO_;
    const uint16_t* kgl = pl + PO_;
    const uint16_t* vg  = ph + 2 * PO_;
    const uint16_t* vgl = pl + 2 * PO_;

    {   // stage Q tile (128 x 64 hi/lo)
        int row = tid >> 1, half = (tid & 1) * 32;
        const uint4* s1 = (const uint4*)(qg  + ((size_t)bh * S_ + q0 + row) * DK_ + half);
        const uint4* s2 = (const uint4*)(qgl + ((size_t)bh * S_ + q0 + row) * DK_ + half);
        uint4* d1 = (uint4*)(QH + row * 72 + half);
        uint4* d2 = (uint4*)(QL + row * 72 + half);
        #pragma unroll
        for (int j = 0; j < 4; j++) { d1[j] = s1[j]; d2[j] = s2[j]; }
    }
    __syncthreads();
    uint32_t qfh[4][4], qfl[4][4];
    {
        int qr = w * 16 + gid;
        #pragma unroll
        for (int ks = 0; ks < 4; ks++) {
            int dc = ks * 16 + 2 * tig;
            qfh[ks][0] = *(const uint32_t*)(QH + qr * 72 + dc);
            qfh[ks][1] = *(const uint32_t*)(QH + (qr + 8) * 72 + dc);
            qfh[ks][2] = *(const uint32_t*)(QH + qr * 72 + dc + 8);
            qfh[ks][3] = *(const uint32_t*)(QH + (qr + 8) * 72 + dc + 8);
            qfl[ks][0] = *(const uint32_t*)(QL + qr * 72 + dc);
            qfl[ks][1] = *(const uint32_t*)(QL + (qr + 8) * 72 + dc);
            qfl[ks][2] = *(const uint32_t*)(QL + qr * 72 + dc + 8);
            qfl[ks][3] = *(const uint32_t*)(QL + (qr + 8) * 72 + dc + 8);
        }
    }
    const int r0 = q0 + w * 16 + gid, r1 = r0 + 8;
    float sum0 = 0.f, sum1 = 0.f, inv0 = 0.f, inv1 = 0.f;
    if (pass) { inv0 = 1.f / rsum[bh * S_ + r0]; inv1 = 1.f / rsum[bh * S_ + r1]; }
    float accv[8][4];
    #pragma unroll
    for (int i = 0; i < 8; i++)
        #pragma unroll
        for (int j = 0; j < 4; j++) accv[i][j] = 0.f;
    uint32_t a01h[4], a01l[4];

    for (int kt = 0; kt < 16; kt++) {
        const int k0 = kt * 128;
        __syncthreads();
        {   // stage K tile
            int row = tid >> 1, half = (tid & 1) * 32;
            const uint4* s1 = (const uint4*)(kg  + ((size_t)bh * S_ + k0 + row) * DK_ + half);
            const uint4* s2 = (const uint4*)(kgl + ((size_t)bh * S_ + k0 + row) * DK_ + half);
            uint4* d1 = (uint4*)(KH + row * 72 + half);
            uint4* d2 = (uint4*)(KL + row * 72 + half);
            #pragma unroll
            for (int j = 0; j < 4; j++) { d1[j] = s1[j]; d2[j] = s2[j]; }
        }
        if (pass) {   // stage V^T (64 dk x 128 tokens, hi/lo)
            int hl = tid & 1, dkh = (tid >> 7) & 1, p2 = (tid >> 1) & 63;
            const uint16_t* vsrc = (hl ? vgl : vg) + ((size_t)bh * S_ + k0 + 2 * p2) * DK_ + dkh * 32;
            uint16_t* vdst = hl ? VTL : VTH;
            const uint32_t* s0 = (const uint32_t*)vsrc;
            const uint32_t* s1 = (const uint32_t*)(vsrc + DK_);
            #pragma unroll
            for (int j = 0; j < 16; j++) {
                uint32_t u0 = s0[j], u1 = s1[j];
                int dk = dkh * 32 + j * 2;
                *(uint32_t*)(vdst + dk * 132 + 2 * p2)       = __byte_perm(u0, u1, 0x5410);
                *(uint32_t*)(vdst + (dk + 1) * 132 + 2 * p2) = __byte_perm(u0, u1, 0x7632);
            }
        }
        __syncthreads();
        for (int nt = 0; nt < 16; nt++) {
            float s[4] = {0.f, 0.f, 0.f, 0.f};
            #pragma unroll
            for (int ks = 0; ks < 4; ks++) {
                int dc = ks * 16 + 2 * tig;
                int kr = nt * 8 + gid;
                uint32_t b0 = *(const uint32_t*)(KH + kr * 72 + dc);
                uint32_t b1 = *(const uint32_t*)(KH + kr * 72 + dc + 8);
                uint32_t c0 = *(const uint32_t*)(KL + kr * 72 + dc);
                uint32_t c1 = *(const uint32_t*)(KL + kr * 72 + dc + 8);
                hmma(s, qfh[ks], b0, b1);
                hmma(s, qfl[ks], b0, b1);
                hmma(s, qfh[ks], c0, c1);
            }
            int col = k0 + nt * 8 + 2 * tig;
            float2 p0 = *(const float2*)(pos + (size_t)r0 * S_ + col);
            float2 p1 = *(const float2*)(pos + (size_t)r1 * S_ + col);
            float e0 = fexp(fmaf(s[0], 0.125f, p0.x));
            float e1 = fexp(fmaf(s[1], 0.125f, p0.y));
            float e2 = fexp(fmaf(s[2], 0.125f, p1.x));
            float e3 = fexp(fmaf(s[3], 0.125f, p1.y));
            if (!pass) { sum0 += e0 + e1; sum1 += e2 + e3; continue; }
            float pa = e0 * inv0, pb = e1 * inv0, pc = e2 * inv1, pd = e3 * inv1;
            *(float2*)(attn + ((size_t)bh * S_ + r0) * S_ + col) = make_float2(pa, pb);
            *(float2*)(attn + ((size_t)bh * S_ + r1) * S_ + col) = make_float2(pc, pd);
            uint32_t h0, l0, h1, l1;
            splitpack(pa, pb, h0, l0);
            splitpack(pc, pd, h1, l1);
            if ((nt & 1) == 0) {
                a01h[0] = h0; a01h[1] = h1; a01l[0] = l0; a01l[1] = l1;
            } else {
                a01h[2] = h0; a01h[3] = h1; a01l[2] = l0; a01l[3] = l1;
                int kc = nt >> 1;
                #pragma unroll
                for (int dt = 0; dt < 8; dt++) {
                    int vr = dt * 8 + gid;
                    uint32_t vb0 = *(const uint32_t*)(VTH + vr * 132 + kc * 16 + 2 * tig);
                    uint32_t vb1 = *(const uint32_t*)(VTH + vr * 132 + kc * 16 + 2 * tig + 8);
                    uint32_t wb0 = *(const uint32_t*)(VTL + vr * 132 + kc * 16 + 2 * tig);
                    uint32_t wb1 = *(const uint32_t*)(VTL + vr * 132 + kc * 16 + 2 * tig + 8);
                    hmma(accv[dt], a01h, vb0, vb1);
                    hmma(accv[dt], a01l, vb0, vb1);
                    hmma(accv[dt], a01h, wb0, wb1);
                }
            }
        }
    }
    if (!pass) {
        sum0 += __shfl_xor_sync(0xffffffffu, sum0, 1);
        sum0 += __shfl_xor_sync(0xffffffffu, sum0, 2);
        sum1 += __shfl_xor_sync(0xffffffffu, sum1, 1);
        sum1 += __shfl_xor_sync(0xffffffffu, sum1, 2);
        if (tig == 0) { rsum[bh * S_ + r0] = sum0; rsum[bh * S_ + r1] = sum1; }
        return;
    }
    const int bb = bh >> 3, h = bh & 7;
    #pragma unroll
    for (int dt = 0; dt < 8; dt++) {
        int col = dt * 8 + 2 * tig;
        uint32_t hh, ll;
        splitpack(accv[dt][0], accv[dt][1], hh, ll);
        *(uint32_t*)(xh + ((size_t)(bb * S_ + r0)) * D_ + h * DK_ + col) = hh;
        *(uint32_t*)(xl + ((size_t)(bb * S_ + r0)) * D_ + h * DK_ + col) = ll;
        splitpack(accv[dt][2], accv[dt][3], hh, ll);
        *(uint32_t*)(xh + ((size_t)(bb * S_ + r1)) * D_ + h * DK_ + col) = hh;
        *(uint32_t*)(xl + ((size_t)(bb * S_ + r1)) * D_ + h * DK_ + col) = ll;
    }
}

// ---------------- launch ----------------
extern "C" void kernel_launch(void* const* d_in, const int* in_sizes, int n_in,
                              void* d_out, int out_size) {
    const float* q     = (const float*)d_in[0];
    const float* k     = (const float*)d_in[1];
    const float* v     = (const float*)d_in[2];
    const float* pos_k = (const float*)d_in[4];
    const float* ln_w  = (const float*)d_in[5];
    const float* ln_b  = (const float*)d_in[6];
    const float* Wq    = (const float*)d_in[7];
    const float* bq    = (const float*)d_in[8];
    const float* Wk    = (const float*)d_in[9];
    const float* bk    = (const float*)d_in[10];
    const float* Wv    = (const float*)d_in[11];
    const float* bv    = (const float*)d_in[12];
    const float* Wo    = (const float*)d_in[13];
    const float* bo    = (const float*)d_in[14];
    float* out = (float*)d_out;

    uint16_t *xnh, *xnl, *wh, *wl, *phh, *phl, *xh, *xl;
    float *rsum, *attn;
    cudaGetSymbolAddress((void**)&xnh, g_xnh);
    cudaGetSymbolAddress((void**)&xnl, g_xnl);
    cudaGetSymbolAddress((void**)&wh, g_wh);
    cudaGetSymbolAddress((void**)&wl, g_wl);
    cudaGetSymbolAddress((void**)&phh, g_phh);
    cudaGetSymbolAddress((void**)&phl, g_phl);
    cudaGetSymbolAddress((void**)&xh, g_xh);
    cudaGetSymbolAddress((void**)&xl, g_xl);
    cudaGetSymbolAddress((void**)&rsum, g_rsum);
    if ((size_t)out_size >= OUT_ELEMS + ATTN_ELEMS) {
        attn = out + OUT_ELEMS;
    } else {
        cudaGetSymbolAddress((void**)&attn, g_attn_scratch);
    }

    cudaFuncSetAttribute(gemm_mma, cudaFuncAttributeMaxDynamicSharedMemorySize, 73728);
    cudaFuncSetAttribute(attn_mma, cudaFuncAttributeMaxDynamicSharedMemorySize, 107520);

    ln_split<<<dim3(TOK_, 3), 128>>>(q, k, v, ln_w, ln_b, xnh, xnl);
    wsplit<<<dim3(512, 4), 128>>>(Wq, Wk, Wv, Wo, wh, wl);

    const size_t XO = (size_t)TOK_ * D_;
    const size_t WO = 512ull * 512ull;
    const float* biases[3] = {bq, bk, bv};
    for (int m = 0; m < 3; m++) {
        gemm_mma<<<dim3(4, 64), 256, 73728>>>(xnh + m * XO, xnl + m * XO,
                                              wh + m * WO, wl + m * WO, biases[m],
                                              phh + m * PO_, phl + m * PO_, nullptr, 1);
    }
    attn_mma<<<dim3(16, 32), 256, 107520>>>(phh, phl, pos_k, attn, rsum, xh, xl, 0);
    attn_mma<<<dim3(16, 32), 256, 107520>>>(phh, phl, pos_k, attn, rsum, xh, xl, 1);
    gemm_mma<<<dim3(4, 64), 256, 73728>>>(xh, xl, wh + 3 * WO, wl + 3 * WO, bo,
                                          nullptr, nullptr, out, 0);
}

// round 6
// speedup vs baseline: 1.1318x; 1.1318x over previous
#include <cuda_runtime.h>
#include <cuda_bf16.h>
#include <cstdint>

#define S_ 2048
#define D_ 512
#define H_ 8
#define DK_ 64
#define BH_ 32
#define TOK_ 8192
#define OUT_ELEMS 4194304ull
#define ATTN_ELEMS 134217728ull
#define PO_ 4194304ull

__device__ uint16_t g_xnh[3ull * TOK_ * D_];
__device__ uint16_t g_xnl[3ull * TOK_ * D_];
__device__ uint16_t g_wh[4ull * 512 * 512];
__device__ uint16_t g_wl[4ull * 512 * 512];
__device__ uint16_t g_phh[3ull * PO_];
__device__ uint16_t g_phl[3ull * PO_];
__device__ uint16_t g_xh[(size_t)TOK_ * D_];
__device__ uint16_t g_xl[(size_t)TOK_ * D_];
__device__ float g_rinv[BH_ * S_];
__device__ float g_attn_scratch[ATTN_ELEMS];

__device__ __forceinline__ void hmma(float c[4], const uint32_t a[4], uint32_t b0, uint32_t b1) {
    asm("mma.sync.aligned.m16n8k16.row.col.f32.bf16.bf16.f32 "
        "{%0,%1,%2,%3},{%4,%5,%6,%7},{%8,%9},{%0,%1,%2,%3};"
        : "+f"(c[0]), "+f"(c[1]), "+f"(c[2]), "+f"(c[3])
        : "r"(a[0]), "r"(a[1]), "r"(a[2]), "r"(a[3]), "r"(b0), "r"(b1));
}
__device__ __forceinline__ void splitpack(float f0, float f1, uint32_t& h, uint32_t& l) {
    asm("cvt.rn.bf16x2.f32 %0, %1, %2;" : "=r"(h) : "f"(f1), "f"(f0));
    float g0 = __uint_as_float(h << 16);
    float g1 = __uint_as_float(h & 0xffff0000u);
    asm("cvt.rn.bf16x2.f32 %0, %1, %2;" : "=r"(l) : "f"(f1 - g1), "f"(f0 - g0));
}
__device__ __forceinline__ float fexp(float x) {
    float t = x * 1.4426950408889634f;
    t = fmaxf(t, -126.0f);
    float z = t + 12582912.0f;
    int   n = (__float_as_int(z) & 0x7FFFFF) - 0x400000;
    float f = t - (z - 12582912.0f);
    float p = 1.5403530e-4f;
    p = fmaf(p, f, 1.3333558e-3f);
    p = fmaf(p, f, 9.6181291e-3f);
    p = fmaf(p, f, 5.5504109e-2f);
    p = fmaf(p, f, 2.4022651e-1f);
    p = fmaf(p, f, 6.9314718e-1f);
    p = fmaf(p, f, 1.0f);
    return __int_as_float(__float_as_int(p) + (n << 23));
}

// ---------------- K1: LayerNorm -> split bf16 ----------------
__global__ void ln_split(const float* __restrict__ q, const float* __restrict__ k,
                         const float* __restrict__ v, const float* __restrict__ w,
                         const float* __restrict__ b,
                         uint16_t* __restrict__ xh, uint16_t* __restrict__ xl) {
    const int row = blockIdx.x, which = blockIdx.y, tid = threadIdx.x;
    const float* src = (which == 0) ? q : (which == 1) ? k : v;
    float4 x = *(const float4*)(src + (size_t)row * D_ + tid * 4);
    float s  = x.x + x.y + x.z + x.w;
    float ss = x.x * x.x + x.y * x.y + x.z * x.z + x.w * x.w;
    __shared__ float red[2][4];
    #pragma unroll
    for (int o = 16; o; o >>= 1) {
        s  += __shfl_xor_sync(0xffffffffu, s, o);
        ss += __shfl_xor_sync(0xffffffffu, ss, o);
    }
    if ((tid & 31) == 0) { red[0][tid >> 5] = s; red[1][tid >> 5] = ss; }
    __syncthreads();
    s  = red[0][0] + red[0][1] + red[0][2] + red[0][3];
    ss = red[1][0] + red[1][1] + red[1][2] + red[1][3];
    const float mu  = s * (1.0f / D_);
    const float var = ss * (1.0f / D_) - mu * mu;
    const float r   = rsqrtf(var + 1e-5f);
    float4 wv = *(const float4*)(w + tid * 4);
    float4 bv = *(const float4*)(b + tid * 4);
    float o0 = (x.x - mu) * r * wv.x + bv.x;
    float o1 = (x.y - mu) * r * wv.y + bv.y;
    float o2 = (x.z - mu) * r * wv.z + bv.z;
    float o3 = (x.w - mu) * r * wv.w + bv.w;
    uint32_t h01, l01, h23, l23;
    splitpack(o0, o1, h01, l01); splitpack(o2, o3, h23, l23);
    size_t base = ((size_t)which * TOK_ + row) * D_ + tid * 4;
    *(uint32_t*)(xh + base) = h01; *(uint32_t*)(xh + base + 2) = h23;
    *(uint32_t*)(xl + base) = l01; *(uint32_t*)(xl + base + 2) = l23;
}

// ---------------- K2: split weights ----------------
__global__ void wsplit(const float* __restrict__ Wq, const float* __restrict__ Wk,
                       const float* __restrict__ Wv, const float* __restrict__ Wo,
                       uint16_t* __restrict__ wh, uint16_t* __restrict__ wl) {
    const int row = blockIdx.x, mat = blockIdx.y, tid = threadIdx.x;
    const float* W = (mat == 0) ? Wq : (mat == 1) ? Wk : (mat == 2) ? Wv : Wo;
    float4 x = *(const float4*)(W + (size_t)row * 512 + tid * 4);
    uint32_t h01, l01, h23, l23;
    splitpack(x.x, x.y, h01, l01); splitpack(x.z, x.w, h23, l23);
    size_t base = ((size_t)mat * 512 + row) * 512 + tid * 4;
    *(uint32_t*)(wh + base) = h01; *(uint32_t*)(wh + base + 2) = h23;
    *(uint32_t*)(wl + base) = l01; *(uint32_t*)(wl + base + 2) = l23;
}

// ---------------- K3/K6: C[8192,512] = A @ W^T + bias (split-bf16 HMMA, chunk 32) ------
__global__ __launch_bounds__(256, 2)
void gemm_mma(const uint16_t* __restrict__ Ah, const uint16_t* __restrict__ Al,
              const uint16_t* __restrict__ Bh, const uint16_t* __restrict__ Bl,
              const float* __restrict__ bias,
              uint16_t* __restrict__ Dh, uint16_t* __restrict__ Dl,
              float* __restrict__ Df, int mode) {
    extern __shared__ uint16_t sm[];
    uint16_t* sAh = sm;
    uint16_t* sAl = sm + 5120;
    uint16_t* sBh = sm + 10240;
    uint16_t* sBl = sm + 15360;
    const int tid = threadIdx.x, w = tid >> 5, lane = tid & 31;
    const int gid = lane >> 2, tig = lane & 3;
    const int n0 = blockIdx.x * 128, m0 = blockIdx.y * 128;
    const int wm = w >> 2, wn = w & 3;
    const int srow = tid >> 1, shalf = (tid & 1) * 16;
    float acc[4][4][4];
    #pragma unroll
    for (int i = 0; i < 4; i++)
        #pragma unroll
        for (int j = 0; j < 4; j++)
            #pragma unroll
            for (int kq = 0; kq < 4; kq++) acc[i][j][kq] = 0.f;

    for (int c = 0; c < 16; c++) {
        __syncthreads();
        {
            const uint4* a  = (const uint4*)(Ah + (size_t)(m0 + srow) * 512 + c * 32 + shalf);
            const uint4* a2 = (const uint4*)(Al + (size_t)(m0 + srow) * 512 + c * 32 + shalf);
            const uint4* b  = (const uint4*)(Bh + (size_t)(n0 + srow) * 512 + c * 32 + shalf);
            const uint4* b2 = (const uint4*)(Bl + (size_t)(n0 + srow) * 512 + c * 32 + shalf);
            uint4* dA  = (uint4*)(sAh + srow * 40 + shalf);
            uint4* dA2 = (uint4*)(sAl + srow * 40 + shalf);
            uint4* dB  = (uint4*)(sBh + srow * 40 + shalf);
            uint4* dB2 = (uint4*)(sBl + srow * 40 + shalf);
            dA[0] = a[0]; dA[1] = a[1]; dA2[0] = a2[0]; dA2[1] = a2[1];
            dB[0] = b[0]; dB[1] = b[1]; dB2[0] = b2[0]; dB2[1] = b2[1];
        }
        __syncthreads();
        #pragma unroll
        for (int ks = 0; ks < 2; ks++) {
            const int dk = ks * 16 + 2 * tig;
            uint32_t ah[4][4], al[4][4], bhf[4][2], blf[4][2];
            #pragma unroll
            for (int mt = 0; mt < 4; mt++) {
                int ar = wm * 64 + mt * 16 + gid;
                ah[mt][0] = *(const uint32_t*)(sAh + ar * 40 + dk);
                ah[mt][1] = *(const uint32_t*)(sAh + (ar + 8) * 40 + dk);
                ah[mt][2] = *(const uint32_t*)(sAh + ar * 40 + dk + 8);
                ah[mt][3] = *(const uint32_t*)(sAh + (ar + 8) * 40 + dk + 8);
                al[mt][0] = *(const uint32_t*)(sAl + ar * 40 + dk);
                al[mt][1] = *(const uint32_t*)(sAl + (ar + 8) * 40 + dk);
                al[mt][2] = *(const uint32_t*)(sAl + ar * 40 + dk + 8);
                al[mt][3] = *(const uint32_t*)(sAl + (ar + 8) * 40 + dk + 8);
            }
            #pragma unroll
            for (int nt = 0; nt < 4; nt++) {
                int br = wn * 32 + nt * 8 + gid;
                bhf[nt][0] = *(const uint32_t*)(sBh + br * 40 + dk);
                bhf[nt][1] = *(const uint32_t*)(sBh + br * 40 + dk + 8);
                blf[nt][0] = *(const uint32_t*)(sBl + br * 40 + dk);
                blf[nt][1] = *(const uint32_t*)(sBl + br * 40 + dk + 8);
            }
            #pragma unroll
            for (int mt = 0; mt < 4; mt++)
                #pragma unroll
                for (int nt = 0; nt < 4; nt++) {
                    hmma(acc[mt][nt], ah[mt], bhf[nt][0], bhf[nt][1]);
                    hmma(acc[mt][nt], al[mt], bhf[nt][0], bhf[nt][1]);
                    hmma(acc[mt][nt], ah[mt], blf[nt][0], blf[nt][1]);
                }
        }
    }
    #pragma unroll
    for (int mt = 0; mt < 4; mt++) {
        int row0 = m0 + wm * 64 + mt * 16 + gid, row1 = row0 + 8;
        #pragma unroll
        for (int nt = 0; nt < 4; nt++) {
            int nc = n0 + wn * 32 + nt * 8 + 2 * tig;
            float b0 = bias[nc], b1 = bias[nc + 1];
            float c00 = acc[mt][nt][0] + b0, c01 = acc[mt][nt][1] + b1;
            float c10 = acc[mt][nt][2] + b0, c11 = acc[mt][nt][3] + b1;
            if (mode == 0) {
                *(float2*)(Df + (size_t)row0 * 512 + nc) = make_float2(c00, c01);
                *(float2*)(Df + (size_t)row1 * 512 + nc) = make_float2(c10, c11);
            } else {
                int h = nc >> 6, dd = nc & 63;
                uint32_t hh, ll;
                int bb = row0 >> 11, tk = row0 & 2047;
                size_t o = (((size_t)(bb * H_ + h)) * S_ + tk) * DK_ + dd;
                splitpack(c00, c01, hh, ll);
                *(uint32_t*)(Dh + o) = hh; *(uint32_t*)(Dl + o) = ll;
                bb = row1 >> 11; tk = row1 & 2047;
                o = (((size_t)(bb * H_ + h)) * S_ + tk) * DK_ + dd;
                splitpack(c10, c11, hh, ll);
                *(uint32_t*)(Dh + o) = hh; *(uint32_t*)(Dl + o) = ll;
            }
        }
    }
}

// ---------------- K4: fused one-pass attention ----------------
// writes raw e=exp(s+pos) to attn, accumulates row sums + unnormalized AV, scales at end.
__global__ __launch_bounds__(256, 2)
void attn_mma(const uint16_t* __restrict__ ph, const uint16_t* __restrict__ pl,
              const float* __restrict__ pos, float* __restrict__ attn,
              float* __restrict__ rinv,
              uint16_t* __restrict__ xh, uint16_t* __restrict__ xl) {
    extern __shared__ uint16_t sm[];
    uint16_t* QH  = sm;            // dead after fragment load; reused by VT
    uint16_t* QL  = sm + 9216;
    uint16_t* VTH = sm;            // 64 x 132
    uint16_t* VTL = sm + 8448;
    uint16_t* KH  = sm + 18432;
    uint16_t* KL  = sm + 27648;
    const int tid = threadIdx.x, w = tid >> 5, lane = tid & 31;
    const int gid = lane >> 2, tig = lane & 3;
    const int qt = blockIdx.x, bh = blockIdx.y, q0 = qt * 128;
    const uint16_t* qg  = ph;
    const uint16_t* qgl = pl;
    const uint16_t* kg  = ph + PO_;
    const uint16_t* kgl = pl + PO_;
    const uint16_t* vg  = ph + 2 * PO_;
    const uint16_t* vgl = pl + 2 * PO_;

    {   // stage Q tile (128 x 64 hi/lo)
        int row = tid >> 1, half = (tid & 1) * 32;
        const uint4* s1 = (const uint4*)(qg  + ((size_t)bh * S_ + q0 + row) * DK_ + half);
        const uint4* s2 = (const uint4*)(qgl + ((size_t)bh * S_ + q0 + row) * DK_ + half);
        uint4* d1 = (uint4*)(QH + row * 72 + half);
        uint4* d2 = (uint4*)(QL + row * 72 + half);
        #pragma unroll
        for (int j = 0; j < 4; j++) { d1[j] = s1[j]; d2[j] = s2[j]; }
    }
    __syncthreads();
    uint32_t qfh[4][4], qfl[4][4];
    {
        int qr = w * 16 + gid;
        #pragma unroll
        for (int ks = 0; ks < 4; ks++) {
            int dc = ks * 16 + 2 * tig;
            qfh[ks][0] = *(const uint32_t*)(QH + qr * 72 + dc);
            qfh[ks][1] = *(const uint32_t*)(QH + (qr + 8) * 72 + dc);
            qfh[ks][2] = *(const uint32_t*)(QH + qr * 72 + dc + 8);
            qfh[ks][3] = *(const uint32_t*)(QH + (qr + 8) * 72 + dc + 8);
            qfl[ks][0] = *(const uint32_t*)(QL + qr * 72 + dc);
            qfl[ks][1] = *(const uint32_t*)(QL + (qr + 8) * 72 + dc);
            qfl[ks][2] = *(const uint32_t*)(QL + qr * 72 + dc + 8);
            qfl[ks][3] = *(const uint32_t*)(QL + (qr + 8) * 72 + dc + 8);
        }
    }
    const int r0 = q0 + w * 16 + gid, r1 = r0 + 8;
    float sum0 = 0.f, sum1 = 0.f;
    float accv[8][4];
    #pragma unroll
    for (int i = 0; i < 8; i++)
        #pragma unroll
        for (int j = 0; j < 4; j++) accv[i][j] = 0.f;
    uint32_t a01h[4], a01l[4];

    for (int kt = 0; kt < 16; kt++) {
        const int k0 = kt * 128;
        __syncthreads();
        {   // stage K tile
            int row = tid >> 1, half = (tid & 1) * 32;
            const uint4* s1 = (const uint4*)(kg  + ((size_t)bh * S_ + k0 + row) * DK_ + half);
            const uint4* s2 = (const uint4*)(kgl + ((size_t)bh * S_ + k0 + row) * DK_ + half);
            uint4* d1 = (uint4*)(KH + row * 72 + half);
            uint4* d2 = (uint4*)(KL + row * 72 + half);
            #pragma unroll
            for (int j = 0; j < 4; j++) { d1[j] = s1[j]; d2[j] = s2[j]; }
        }
        {   // stage V^T (64 dk x 128 tokens, hi/lo)
            int hl = tid & 1, dkh = (tid >> 7) & 1, p2 = (tid >> 1) & 63;
            const uint16_t* vsrc = (hl ? vgl : vg) + ((size_t)bh * S_ + k0 + 2 * p2) * DK_ + dkh * 32;
            uint16_t* vdst = hl ? VTL : VTH;
            const uint32_t* s0 = (const uint32_t*)vsrc;
            const uint32_t* s1 = (const uint32_t*)(vsrc + DK_);
            #pragma unroll
            for (int j = 0; j < 16; j++) {
                uint32_t u0 = s0[j], u1 = s1[j];
                int dk = dkh * 32 + j * 2;
                *(uint32_t*)(vdst + dk * 132 + 2 * p2)       = __byte_perm(u0, u1, 0x5410);
                *(uint32_t*)(vdst + (dk + 1) * 132 + 2 * p2) = __byte_perm(u0, u1, 0x7632);
            }
        }
        __syncthreads();
        for (int nt = 0; nt < 16; nt++) {
            float s[4] = {0.f, 0.f, 0.f, 0.f};
            #pragma unroll
            for (int ks = 0; ks < 4; ks++) {
                int dc = ks * 16 + 2 * tig;
                int kr = nt * 8 + gid;
                uint32_t b0 = *(const uint32_t*)(KH + kr * 72 + dc);
                uint32_t b1 = *(const uint32_t*)(KH + kr * 72 + dc + 8);
                uint32_t c0 = *(const uint32_t*)(KL + kr * 72 + dc);
                uint32_t c1 = *(const uint32_t*)(KL + kr * 72 + dc + 8);
                hmma(s, qfh[ks], b0, b1);
                hmma(s, qfl[ks], b0, b1);
                hmma(s, qfh[ks], c0, c1);
            }
            int col = k0 + nt * 8 + 2 * tig;
            float2 p0 = *(const float2*)(pos + (size_t)r0 * S_ + col);
            float2 p1 = *(const float2*)(pos + (size_t)r1 * S_ + col);
            float e0 = fexp(fmaf(s[0], 0.125f, p0.x));
            float e1 = fexp(fmaf(s[1], 0.125f, p0.y));
            float e2 = fexp(fmaf(s[2], 0.125f, p1.x));
            float e3 = fexp(fmaf(s[3], 0.125f, p1.y));
            sum0 += e0 + e1; sum1 += e2 + e3;
            *(float2*)(attn + ((size_t)bh * S_ + r0) * S_ + col) = make_float2(e0, e1);
            *(float2*)(attn + ((size_t)bh * S_ + r1) * S_ + col) = make_float2(e2, e3);
            uint32_t h0, l0, h1, l1;
            splitpack(e0, e1, h0, l0);
            splitpack(e2, e3, h1, l1);
            if ((nt & 1) == 0) {
                a01h[0] = h0; a01h[1] = h1; a01l[0] = l0; a01l[1] = l1;
            } else {
                a01h[2] = h0; a01h[3] = h1; a01l[2] = l0; a01l[3] = l1;
                int kc = nt >> 1;
                #pragma unroll
                for (int dt = 0; dt < 8; dt++) {
                    int vr = dt * 8 + gid;
                    uint32_t vb0 = *(const uint32_t*)(VTH + vr * 132 + kc * 16 + 2 * tig);
                    uint32_t vb1 = *(const uint32_t*)(VTH + vr * 132 + kc * 16 + 2 * tig + 8);
                    uint32_t wb0 = *(const uint32_t*)(VTL + vr * 132 + kc * 16 + 2 * tig);
                    uint32_t wb1 = *(const uint32_t*)(VTL + vr * 132 + kc * 16 + 2 * tig + 8);
                    hmma(accv[dt], a01h, vb0, vb1);
                    hmma(accv[dt], a01l, vb0, vb1);
                    hmma(accv[dt], a01h, wb0, wb1);
                }
            }
        }
    }
    sum0 += __shfl_xor_sync(0xffffffffu, sum0, 1);
    sum0 += __shfl_xor_sync(0xffffffffu, sum0, 2);
    sum1 += __shfl_xor_sync(0xffffffffu, sum1, 1);
    sum1 += __shfl_xor_sync(0xffffffffu, sum1, 2);
    float inv0 = 1.f / sum0, inv1 = 1.f / sum1;
    if (tig == 0) { rinv[bh * S_ + r0] = inv0; rinv[bh * S_ + r1] = inv1; }
    const int bb = bh >> 3, h = bh & 7;
    #pragma unroll
    for (int dt = 0; dt < 8; dt++) {
        int col = dt * 8 + 2 * tig;
        uint32_t hh, ll;
        splitpack(accv[dt][0] * inv0, accv[dt][1] * inv0, hh, ll);
        *(uint32_t*)(xh + ((size_t)(bb * S_ + r0)) * D_ + h * DK_ + col) = hh;
        *(uint32_t*)(xl + ((size_t)(bb * S_ + r0)) * D_ + h * DK_ + col) = ll;
        splitpack(accv[dt][2] * inv1, accv[dt][3] * inv1, hh, ll);
        *(uint32_t*)(xh + ((size_t)(bb * S_ + r1)) * D_ + h * DK_ + col) = hh;
        *(uint32_t*)(xl + ((size_t)(bb * S_ + r1)) * D_ + h * DK_ + col) = ll;
    }
}

// ---------------- K5: rescale attn rows by rinv ----------------
__global__ void rescale_k(float* __restrict__ attn, const float* __restrict__ rinv) {
    const int row = blockIdx.x, bh = blockIdx.y, tid = threadIdx.x;
    const float inv = rinv[bh * S_ + row];
    float4* p = (float4*)(attn + ((size_t)bh * S_ + row) * S_) + tid;
    float4 a = p[0], b = p[256];
    a.x *= inv; a.y *= inv; a.z *= inv; a.w *= inv;
    b.x *= inv; b.y *= inv; b.z *= inv; b.w *= inv;
    p[0] = a; p[256] = b;
}

// ---------------- launch ----------------
extern "C" void kernel_launch(void* const* d_in, const int* in_sizes, int n_in,
                              void* d_out, int out_size) {
    const float* q     = (const float*)d_in[0];
    const float* k     = (const float*)d_in[1];
    const float* v     = (const float*)d_in[2];
    const float* pos_k = (const float*)d_in[4];
    const float* ln_w  = (const float*)d_in[5];
    const float* ln_b  = (const float*)d_in[6];
    const float* Wq    = (const float*)d_in[7];
    const float* bq    = (const float*)d_in[8];
    const float* Wk    = (const float*)d_in[9];
    const float* bk    = (const float*)d_in[10];
    const float* Wv    = (const float*)d_in[11];
    const float* bv    = (const float*)d_in[12];
    const float* Wo    = (const float*)d_in[13];
    const float* bo    = (const float*)d_in[14];
    float* out = (float*)d_out;

    uint16_t *xnh, *xnl, *wh, *wl, *phh, *phl, *xh, *xl;
    float *rinv, *attn;
    cudaGetSymbolAddress((void**)&xnh, g_xnh);
    cudaGetSymbolAddress((void**)&xnl, g_xnl);
    cudaGetSymbolAddress((void**)&wh, g_wh);
    cudaGetSymbolAddress((void**)&wl, g_wl);
    cudaGetSymbolAddress((void**)&phh, g_phh);
    cudaGetSymbolAddress((void**)&phl, g_phl);
    cudaGetSymbolAddress((void**)&xh, g_xh);
    cudaGetSymbolAddress((void**)&xl, g_xl);
    cudaGetSymbolAddress((void**)&rinv, g_rinv);
    if ((size_t)out_size >= OUT_ELEMS + ATTN_ELEMS) {
        attn = out + OUT_ELEMS;
    } else {
        cudaGetSymbolAddress((void**)&attn, g_attn_scratch);
    }

    cudaFuncSetAttribute(gemm_mma, cudaFuncAttributeMaxDynamicSharedMemorySize, 40960);
    cudaFuncSetAttribute(attn_mma, cudaFuncAttributeMaxDynamicSharedMemorySize, 73728);

    ln_split<<<dim3(TOK_, 3), 128>>>(q, k, v, ln_w, ln_b, xnh, xnl);
    wsplit<<<dim3(512, 4), 128>>>(Wq, Wk, Wv, Wo, wh, wl);

    const size_t XO = (size_t)TOK_ * D_;
    const size_t WO = 512ull * 512ull;
    const float* biases[3] = {bq, bk, bv};
    for (int m = 0; m < 3; m++) {
        gemm_mma<<<dim3(4, 64), 256, 40960>>>(xnh + m * XO, xnl + m * XO,
                                              wh + m * WO, wl + m * WO, biases[m],
                                              phh + m * PO_, phl + m * PO_, nullptr, 1);
    }
    attn_mma<<<dim3(16, 32), 256, 73728>>>(phh, phl, pos_k, attn, rinv, xh, xl);
    rescale_k<<<dim3(S_, BH_), 256>>>(attn, rinv);
    gemm_mma<<<dim3(4, 64), 256, 40960>>>(xh, xl, wh + 3 * WO, wl + 3 * WO, bo,
                                          nullptr, nullptr, out, 0);
}